// round 8
// baseline (speedup 1.0000x reference)
#include <cuda_runtime.h>
#include <cuda_fp16.h>

// Problem constants (fixed by the reference)
#define N_NODES 100000
#define N_EDGES 50000
#define M_INC   1600000
#define D       64
#define DCH     8          // 16B chunks per fp16 row (64 halves = 8 x uint4)
#define DC4     16         // float4 chunks per f32 row
#define MH      (M_INC / 2)

// bit-cast helpers
__device__ __forceinline__ unsigned h2_as_u(__half2 h) {
    return *reinterpret_cast<unsigned*>(&h);
}
__device__ __forceinline__ __half2 u_as_h2(unsigned u) {
    return *reinterpret_cast<__half2*>(&u);
}

// ---------------------------------------------------------------------------
// Scratch (__device__ globals; zero-initialized at load).
// INVARIANT: g_Dn and g_Be are zero at every kernel_launch entry —
// k_scale_ef and k_final restore them to zero after consuming them.
// ---------------------------------------------------------------------------
__device__ float  g_Dn[N_NODES];             // weighted node degree
__device__ float  g_Be[N_EDGES];             // edge cardinality
__device__ __half g_xh[(long)N_NODES * D];   // x in fp16
__device__ __half g_ef[(long)N_EDGES * D];   // edge features fp16
__device__ __half g_h [(long)N_NODES * D];   // unscaled node accumulator fp16

// ---------------------------------------------------------------------------
// K0 (prep): degree atomics + convert x->fp16 + zero ef/h.
// Atomics (LTS atomic ALU) overlap with the streaming traffic (LTS sectors).
// Requires g_Be/g_Dn == 0 on entry (module-load init / self-restoring).
// ---------------------------------------------------------------------------
__global__ void k_prep(const float* __restrict__ x,
                       const int* __restrict__ ni, const int* __restrict__ ei,
                       const float* __restrict__ w) {
    long i = blockIdx.x * (long)blockDim.x + threadIdx.x;
    long stride = (long)gridDim.x * blockDim.x;

    // degrees: 4 incidences per iteration
    for (long j = i; j < M_INC / 4; j += stride) {
        int4 n4 = ((const int4*)ni)[j];
        int4 e4 = ((const int4*)ei)[j];
        float w0 = __ldg(&w[e4.x]);
        float w1 = __ldg(&w[e4.y]);
        float w2 = __ldg(&w[e4.z]);
        float w3 = __ldg(&w[e4.w]);
        atomicAdd(&g_Be[e4.x], 1.0f);
        atomicAdd(&g_Be[e4.y], 1.0f);
        atomicAdd(&g_Be[e4.z], 1.0f);
        atomicAdd(&g_Be[e4.w], 1.0f);
        atomicAdd(&g_Dn[n4.x], w0);
        atomicAdd(&g_Dn[n4.y], w1);
        atomicAdd(&g_Dn[n4.z], w2);
        atomicAdd(&g_Dn[n4.w], w3);
    }

    // convert x -> fp16
    const long XH8 = (long)N_NODES * D / 8;
    for (long j = i; j < XH8; j += stride) {
        float4 a = ((const float4*)x)[j * 2];
        float4 b = ((const float4*)x)[j * 2 + 1];
        uint4 u;
        u.x = h2_as_u(__floats2half2_rn(a.x, a.y));
        u.y = h2_as_u(__floats2half2_rn(a.z, a.w));
        u.z = h2_as_u(__floats2half2_rn(b.x, b.y));
        u.w = h2_as_u(__floats2half2_rn(b.z, b.w));
        ((uint4*)g_xh)[j] = u;
    }

    // zero accumulators
    const long EF8 = (long)N_EDGES * D / 8;
    const long H8  = (long)N_NODES * D / 8;
    uint4 z = make_uint4(0u, 0u, 0u, 0u);
    for (long j = i; j < EF8; j += stride) ((uint4*)g_ef)[j] = z;
    for (long j = i; j < H8;  j += stride) ((uint4*)g_h)[j]  = z;
}

// ---------------------------------------------------------------------------
// K1: stage 1 — pure scatter: ef[e] += xh[n]  (fp16x2 vector REDG)
// thread t -> chunk c = t&7 (16B), incidences m0 = t>>3 and m1 = m0 + M/2.
// ---------------------------------------------------------------------------
__global__ void k_stage1(const int* __restrict__ ni, const int* __restrict__ ei) {
    int t = blockIdx.x * blockDim.x + threadIdx.x;
    if (t >= MH * DCH) return;
    int c  = t & 7;
    int m0 = t >> 3;
    int m1 = m0 + MH;

    int n0 = __ldg(&ni[m0]);
    int e0 = __ldg(&ei[m0]);
    int n1 = __ldg(&ni[m1]);
    int e1 = __ldg(&ei[m1]);

    uint4 u0 = __ldg(&((const uint4*)g_xh)[(long)n0 * DCH + c]);
    uint4 u1 = __ldg(&((const uint4*)g_xh)[(long)n1 * DCH + c]);

    __half* d0 = &g_ef[(long)e0 * D + c * 8];
    __half* d1 = &g_ef[(long)e1 * D + c * 8];
    asm volatile("red.global.add.noftz.v4.f16x2 [%0], {%1,%2,%3,%4};"
                 :: "l"(d0), "r"(u0.x), "r"(u0.y), "r"(u0.z), "r"(u0.w) : "memory");
    asm volatile("red.global.add.noftz.v4.f16x2 [%0], {%1,%2,%3,%4};"
                 :: "l"(d1), "r"(u1.x), "r"(u1.y), "r"(u1.z), "r"(u1.w) : "memory");
}

// ---------------------------------------------------------------------------
// K2: scale ef rows by 1/Be (safe recip inline), then restore Be[e]=0.
// One uint4 chunk per thread; the 8 lanes of an edge sit in one warp, so the
// c==0 zero-store is ordered after all lanes' Be load (program order).
// ---------------------------------------------------------------------------
__global__ void k_scale_ef() {
    int t = blockIdx.x * blockDim.x + threadIdx.x;
    if (t >= N_EDGES * DCH) return;
    int e = t >> 3;
    int c = t & 7;
    float b = g_Be[e];
    float br = (b > 0.f) ? (1.0f / b) : 0.f;
    __half2 bh = __float2half2_rn(br);

    uint4 u = ((const uint4*)g_ef)[t];
    u.x = h2_as_u(__hmul2(u_as_h2(u.x), bh));
    u.y = h2_as_u(__hmul2(u_as_h2(u.y), bh));
    u.z = h2_as_u(__hmul2(u_as_h2(u.z), bh));
    u.w = h2_as_u(__hmul2(u_as_h2(u.w), bh));
    ((uint4*)g_ef)[t] = u;

    if (c == 0) g_Be[e] = 0.f;   // restore invariant for next call
}

// ---------------------------------------------------------------------------
// K3: stage 2 — pure scatter: h[n] += ef[e]  (fp16x2 vector REDG)
// ---------------------------------------------------------------------------
__global__ void k_stage2(const int* __restrict__ ni, const int* __restrict__ ei) {
    int t = blockIdx.x * blockDim.x + threadIdx.x;
    if (t >= MH * DCH) return;
    int c  = t & 7;
    int m0 = t >> 3;
    int m1 = m0 + MH;

    int n0 = __ldg(&ni[m0]);
    int e0 = __ldg(&ei[m0]);
    int n1 = __ldg(&ni[m1]);
    int e1 = __ldg(&ei[m1]);

    uint4 u0 = ((const uint4*)g_ef)[(long)e0 * DCH + c];
    uint4 u1 = ((const uint4*)g_ef)[(long)e1 * DCH + c];

    __half* d0 = &g_h[(long)n0 * D + c * 8];
    __half* d1 = &g_h[(long)n1 * D + c * 8];
    asm volatile("red.global.add.noftz.v4.f16x2 [%0], {%1,%2,%3,%4};"
                 :: "l"(d0), "r"(u0.x), "r"(u0.y), "r"(u0.z), "r"(u0.w) : "memory");
    asm volatile("red.global.add.noftz.v4.f16x2 [%0], {%1,%2,%3,%4};"
                 :: "l"(d1), "r"(u1.x), "r"(u1.y), "r"(u1.z), "r"(u1.w) : "memory");
}

// ---------------------------------------------------------------------------
// K4: final — out = 0.5*x + (0.5/Dn)*h, then restore Dn[node]=0.
// 16 lanes per node (one warp), so the lane-0 zero-store is ordered after
// all lanes' Dn load.
// ---------------------------------------------------------------------------
__global__ void k_final(const float* __restrict__ x, float* __restrict__ out) {
    int t = blockIdx.x * blockDim.x + threadIdx.x;
    if (t >= N_NODES * DC4) return;
    int node = t >> 4;
    float dnv = g_Dn[node];
    float dn = (dnv > 0.f) ? (0.5f / dnv) : 0.f;

    float4 xv = ((const float4*)x)[t];
    uint2 hu = ((const uint2*)g_h)[t];
    float2 h01 = __half22float2(u_as_h2(hu.x));
    float2 h23 = __half22float2(u_as_h2(hu.y));

    float4 o;
    o.x = 0.5f * xv.x + dn * h01.x;
    o.y = 0.5f * xv.y + dn * h01.y;
    o.z = 0.5f * xv.z + dn * h23.x;
    o.w = 0.5f * xv.w + dn * h23.y;
    ((float4*)out)[t] = o;

    if ((t & 15) == 0) g_Dn[node] = 0.f;   // restore invariant for next call
}

// ---------------------------------------------------------------------------
extern "C" void kernel_launch(void* const* d_in, const int* in_sizes, int n_in,
                              void* d_out, int out_size) {
    const float* x  = (const float*)d_in[0];
    const int*   ni = (const int*)d_in[1];
    const int*   ei = (const int*)d_in[2];
    const float* w  = (const float*)d_in[3];
    float* out = (float*)d_out;

    const int T = 256;
    int stage_threads = MH * DCH;                 // 6.4M threads

    k_prep<<<2048, T>>>(x, ni, ei, w);
    k_stage1<<<(stage_threads + T - 1) / T, T>>>(ni, ei);
    k_scale_ef<<<(N_EDGES * DCH + T - 1) / T, T>>>();
    k_stage2<<<(stage_threads + T - 1) / T, T>>>(ni, ei);
    k_final<<<(N_NODES * DC4 + T - 1) / T, T>>>(x, out);
}

// round 9
// speedup vs baseline: 1.0193x; 1.0193x over previous
#include <cuda_runtime.h>
#include <cuda_fp16.h>

// Problem constants (fixed by the reference)
#define N_NODES 100000
#define N_EDGES 50000
#define M_INC   1600000
#define D       64
#define DCH     8          // 16B chunks per fp16 row (64 halves = 8 x uint4)
#define DC4     16         // float4 chunks per f32 row
#define MH      (M_INC / 2)

// bit-cast helpers
__device__ __forceinline__ unsigned h2_as_u(__half2 h) {
    return *reinterpret_cast<unsigned*>(&h);
}
__device__ __forceinline__ __half2 u_as_h2(unsigned u) {
    return *reinterpret_cast<__half2*>(&u);
}

// ---------------------------------------------------------------------------
// Scratch (__device__ globals; zero-initialized at load).
// INVARIANT: g_Dn and g_Be are zero at every kernel_launch entry —
// k_scale_ef and k_final restore them to zero after consuming them.
// ---------------------------------------------------------------------------
__device__ float  g_Dn[N_NODES];             // weighted node degree
__device__ float  g_Be[N_EDGES];             // edge cardinality
__device__ __half g_xh[(long)N_NODES * D];   // x in fp16
__device__ __half g_ef[(long)N_EDGES * D];   // edge features fp16
__device__ __half g_h [(long)N_NODES * D];   // unscaled node accumulator fp16

// ---------------------------------------------------------------------------
// K0 (prep): convert x->fp16, zero ef/h. No atomics here.
// ---------------------------------------------------------------------------
__global__ void k_prep(const float* __restrict__ x) {
    long i = blockIdx.x * (long)blockDim.x + threadIdx.x;
    long stride = (long)gridDim.x * blockDim.x;

    const long XH8 = (long)N_NODES * D / 8;
    for (long j = i; j < XH8; j += stride) {
        float4 a = ((const float4*)x)[j * 2];
        float4 b = ((const float4*)x)[j * 2 + 1];
        uint4 u;
        u.x = h2_as_u(__floats2half2_rn(a.x, a.y));
        u.y = h2_as_u(__floats2half2_rn(a.z, a.w));
        u.z = h2_as_u(__floats2half2_rn(b.x, b.y));
        u.w = h2_as_u(__floats2half2_rn(b.z, b.w));
        ((uint4*)g_xh)[j] = u;
    }

    const long EF8 = (long)N_EDGES * D / 8;
    const long H8  = (long)N_NODES * D / 8;
    uint4 z = make_uint4(0u, 0u, 0u, 0u);
    for (long j = i; j < EF8; j += stride) ((uint4*)g_ef)[j] = z;
    for (long j = i; j < H8;  j += stride) ((uint4*)g_h)[j]  = z;
}

// ---------------------------------------------------------------------------
// K1: stage 1 — scatter ef[e] += xh[n] (fp16x2 vector REDG).
// Lane c==0 additionally accumulates BOTH degree reductions (Be count and
// weighted Dn); these ride in the shadow of the feature-REDG serialization.
// thread t -> chunk c = t&7 (16B), incidences m0 = t>>3 and m1 = m0 + M/2.
// ---------------------------------------------------------------------------
__global__ void k_stage1(const int* __restrict__ ni, const int* __restrict__ ei,
                         const float* __restrict__ w) {
    int t = blockIdx.x * blockDim.x + threadIdx.x;
    if (t >= MH * DCH) return;
    int c  = t & 7;
    int m0 = t >> 3;
    int m1 = m0 + MH;

    int n0 = __ldg(&ni[m0]);
    int e0 = __ldg(&ei[m0]);
    int n1 = __ldg(&ni[m1]);
    int e1 = __ldg(&ei[m1]);

    uint4 u0 = __ldg(&((const uint4*)g_xh)[(long)n0 * DCH + c]);
    uint4 u1 = __ldg(&((const uint4*)g_xh)[(long)n1 * DCH + c]);

    __half* d0 = &g_ef[(long)e0 * D + c * 8];
    __half* d1 = &g_ef[(long)e1 * D + c * 8];
    asm volatile("red.global.add.noftz.v4.f16x2 [%0], {%1,%2,%3,%4};"
                 :: "l"(d0), "r"(u0.x), "r"(u0.y), "r"(u0.z), "r"(u0.w) : "memory");
    asm volatile("red.global.add.noftz.v4.f16x2 [%0], {%1,%2,%3,%4};"
                 :: "l"(d1), "r"(u1.x), "r"(u1.y), "r"(u1.z), "r"(u1.w) : "memory");

    if (c == 0) {
        float w0 = __ldg(&w[e0]);
        float w1 = __ldg(&w[e1]);
        atomicAdd(&g_Be[e0], 1.0f);
        atomicAdd(&g_Be[e1], 1.0f);
        atomicAdd(&g_Dn[n0], w0);
        atomicAdd(&g_Dn[n1], w1);
    }
}

// ---------------------------------------------------------------------------
// K2: scale ef rows by 1/Be (safe recip inline), then restore Be[e]=0.
// 8 lanes of an edge sit in one warp; the c==0 zero-store is after all
// lanes' Be load in the warp's instruction stream.
// ---------------------------------------------------------------------------
__global__ void k_scale_ef() {
    int t = blockIdx.x * blockDim.x + threadIdx.x;
    if (t >= N_EDGES * DCH) return;
    int e = t >> 3;
    int c = t & 7;
    float b = g_Be[e];
    float br = (b > 0.f) ? (1.0f / b) : 0.f;
    __half2 bh = __float2half2_rn(br);

    uint4 u = ((const uint4*)g_ef)[t];
    u.x = h2_as_u(__hmul2(u_as_h2(u.x), bh));
    u.y = h2_as_u(__hmul2(u_as_h2(u.y), bh));
    u.z = h2_as_u(__hmul2(u_as_h2(u.z), bh));
    u.w = h2_as_u(__hmul2(u_as_h2(u.w), bh));
    ((uint4*)g_ef)[t] = u;

    if (c == 0) g_Be[e] = 0.f;   // restore invariant for next call
}

// ---------------------------------------------------------------------------
// K3: stage 2 — pure scatter: h[n] += ef[e]  (fp16x2 vector REDG)
// ---------------------------------------------------------------------------
__global__ void k_stage2(const int* __restrict__ ni, const int* __restrict__ ei) {
    int t = blockIdx.x * blockDim.x + threadIdx.x;
    if (t >= MH * DCH) return;
    int c  = t & 7;
    int m0 = t >> 3;
    int m1 = m0 + MH;

    int n0 = __ldg(&ni[m0]);
    int e0 = __ldg(&ei[m0]);
    int n1 = __ldg(&ni[m1]);
    int e1 = __ldg(&ei[m1]);

    uint4 u0 = ((const uint4*)g_ef)[(long)e0 * DCH + c];
    uint4 u1 = ((const uint4*)g_ef)[(long)e1 * DCH + c];

    __half* d0 = &g_h[(long)n0 * D + c * 8];
    __half* d1 = &g_h[(long)n1 * D + c * 8];
    asm volatile("red.global.add.noftz.v4.f16x2 [%0], {%1,%2,%3,%4};"
                 :: "l"(d0), "r"(u0.x), "r"(u0.y), "r"(u0.z), "r"(u0.w) : "memory");
    asm volatile("red.global.add.noftz.v4.f16x2 [%0], {%1,%2,%3,%4};"
                 :: "l"(d1), "r"(u1.x), "r"(u1.y), "r"(u1.z), "r"(u1.w) : "memory");
}

// ---------------------------------------------------------------------------
// K4: final — out = 0.5*x + (0.5/Dn)*h, then restore Dn[node]=0.
// 16 lanes per node (one warp), lane-0 zero-store after all lanes' load.
// ---------------------------------------------------------------------------
__global__ void k_final(const float* __restrict__ x, float* __restrict__ out) {
    int t = blockIdx.x * blockDim.x + threadIdx.x;
    if (t >= N_NODES * DC4) return;
    int node = t >> 4;
    float dnv = g_Dn[node];
    float dn = (dnv > 0.f) ? (0.5f / dnv) : 0.f;

    float4 xv = ((const float4*)x)[t];
    uint2 hu = ((const uint2*)g_h)[t];
    float2 h01 = __half22float2(u_as_h2(hu.x));
    float2 h23 = __half22float2(u_as_h2(hu.y));

    float4 o;
    o.x = 0.5f * xv.x + dn * h01.x;
    o.y = 0.5f * xv.y + dn * h01.y;
    o.z = 0.5f * xv.z + dn * h23.x;
    o.w = 0.5f * xv.w + dn * h23.y;
    ((float4*)out)[t] = o;

    if ((t & 15) == 0) g_Dn[node] = 0.f;   // restore invariant for next call
}

// ---------------------------------------------------------------------------
extern "C" void kernel_launch(void* const* d_in, const int* in_sizes, int n_in,
                              void* d_out, int out_size) {
    const float* x  = (const float*)d_in[0];
    const int*   ni = (const int*)d_in[1];
    const int*   ei = (const int*)d_in[2];
    const float* w  = (const float*)d_in[3];
    float* out = (float*)d_out;

    const int T = 256;
    int stage_threads = MH * DCH;                 // 6.4M threads

    k_prep<<<2048, T>>>(x);
    k_stage1<<<(stage_threads + T - 1) / T, T>>>(ni, ei, w);
    k_scale_ef<<<(N_EDGES * DCH + T - 1) / T, T>>>();
    k_stage2<<<(stage_threads + T - 1) / T, T>>>(ni, ei);
    k_final<<<(N_NODES * DC4 + T - 1) / T, T>>>(x, out);
}